// round 6
// baseline (speedup 1.0000x reference)
#include <cuda_runtime.h>

namespace {

constexpr int Bb  = 2;    // batch
constexpr int Nn  = 512;  // context nodes
constexpr int Mm  = 256;  // target nodes
constexpr int Dd  = 32;   // per-hop feature dim
constexpr int Tt  = 128;  // time
constexpr int ORD = 2;
constexpr int CC  = 96;   // (ORD+1)*Dd
constexpr int CO  = 64;

constexpr int BM   = 128; // m-tile per CTA
constexpr int BK   = 32;  // n-chunk
constexpr int BDIM = 256;

struct Smem {
    float g[Nn][Dd];          // mask-folded context features for this (b,t): 64 KB
    float adjt[ORD][BK][BM];  // transposed adj chunk: 32 KB
    float msk[Nn];            // (1 - mask): 2 KB
    float Wt[CC][CO];         // W transposed [c][o]: 24 KB
    float agg[BM][CC];        // concat channels for MLP: 48 KB
};
constexpr int SMEM_BYTES = (int)sizeof(Smem);  // ~170 KB

__global__ void __launch_bounds__(BDIM, 1)
graph_agg_kernel(const float* __restrict__ fc,    // [B,N,D,T]
                 const float* __restrict__ ft,    // [B,M,D,T]
                 const float* __restrict__ adj,   // [B,ORD,M,N]
                 const float* __restrict__ mask,  // [B,T,N]
                 const float* __restrict__ Wm,    // [CO,CC]
                 const float* __restrict__ bm,    // [CO]
                 float* __restrict__ out)         // [B,M,CO,T]
{
    extern __shared__ char smraw[];
    Smem& S = *reinterpret_cast<Smem*>(smraw);

    const int t   = blockIdx.x;   // 0..T-1
    const int mt  = blockIdx.y;   // 0..Mm/BM-1
    const int b   = blockIdx.z;   // 0..B-1
    const int tid = threadIdx.x;

    // ---------------- prologue: W (transposed), mask, g ----------------
    for (int i = tid; i < CO * CC; i += BDIM) {
        int o = i / CC, c = i % CC;
        S.Wt[c][o] = Wm[i];
    }
    {
        const float* maskp = mask + (b * Tt + t) * Nn;
        #pragma unroll
        for (int r = 0; r < Nn / BDIM; ++r) {
            int n = tid + r * BDIM;              // coalesced
            S.msk[n] = 1.0f - maskp[n];
        }
    }
    __syncthreads();
    {
        // g[n][d] = msk[n] * fc[b][n][d][t]; lanes vary d -> conflict-free STS
        const int dl = tid & 31;        // d lane
        const int ng = tid >> 5;        // 8 n-groups
        #pragma unroll
        for (int r = 0; r < Nn / 8; ++r) {
            int n = ng + r * 8;
            float mv = S.msk[n];
            float v = fc[((b * Nn + n) * Dd + dl) * Tt + t];
            S.g[n][dl] = mv * v;
        }
    }

    // ---------------- main loop: raw = adj @ g, denom = adj @ msk ----------------
    const int kk = tid >> 7;          // order handled by this thread (0/1)
    const int mg = (tid >> 3) & 15;   // m-group (8 rows each)
    const int dg = tid & 7;           // d-group (4 cols each)

    float4 acc[8];
    float  dacc[8];
    #pragma unroll
    for (int i = 0; i < 8; ++i) { acc[i] = make_float4(0.f, 0.f, 0.f, 0.f); dacc[i] = 0.f; }

    const int kL = tid >> 7;          // loader mapping: k
    const int mL = tid & 127;         //                 m within tile
    const float* adjp = adj + (size_t)(((b * ORD + kL) * Mm + mt * BM + mL)) * Nn;

    for (int ch = 0; ch < Nn / BK; ++ch) {
        __syncthreads();  // previous compute done before overwriting adjt (also orders prologue)
        #pragma unroll
        for (int j = 0; j < BK / 4; ++j) {
            float4 v = *reinterpret_cast<const float4*>(adjp + ch * BK + j * 4);
            S.adjt[kL][j * 4 + 0][mL] = v.x;
            S.adjt[kL][j * 4 + 1][mL] = v.y;
            S.adjt[kL][j * 4 + 2][mL] = v.z;
            S.adjt[kL][j * 4 + 3][mL] = v.w;
        }
        __syncthreads();

        #pragma unroll 8
        for (int nn = 0; nn < BK; ++nn) {
            const int n = ch * BK + nn;
            const float mv = S.msk[n];
            const float4 gv = *reinterpret_cast<const float4*>(&S.g[n][dg * 4]);
            const float* ap = &S.adjt[kk][nn][mg * 8];
            const float4 a0 = *reinterpret_cast<const float4*>(ap);
            const float4 a1 = *reinterpret_cast<const float4*>(ap + 4);
            const float av[8] = {a0.x, a0.y, a0.z, a0.w, a1.x, a1.y, a1.z, a1.w};
            #pragma unroll
            for (int i = 0; i < 8; ++i) {
                acc[i].x = fmaf(av[i], gv.x, acc[i].x);
                acc[i].y = fmaf(av[i], gv.y, acc[i].y);
                acc[i].z = fmaf(av[i], gv.z, acc[i].z);
                acc[i].w = fmaf(av[i], gv.w, acc[i].w);
                dacc[i]  = fmaf(av[i], mv,   dacc[i]);
            }
        }
    }

    // ---------------- epilogue: agg = ft + raw/(denom+1) -> SMEM concat ----------------
    {
        const float* ftb = ft + (size_t)((b * Mm + mt * BM) * Dd) * Tt + t;
        #pragma unroll
        for (int i = 0; i < 8; ++i) {
            const int m = mg * 8 + i;
            const float inv = 1.0f / (dacc[i] + 1.0f);
            const float* fr = ftb + (size_t)(m * Dd + dg * 4) * Tt;
            const float f0 = fr[0];
            const float f1 = fr[Tt];
            const float f2 = fr[2 * Tt];
            const float f3 = fr[3 * Tt];
            float4 ag;
            ag.x = fmaf(acc[i].x, inv, f0);
            ag.y = fmaf(acc[i].y, inv, f1);
            ag.z = fmaf(acc[i].z, inv, f2);
            ag.w = fmaf(acc[i].w, inv, f3);
            *reinterpret_cast<float4*>(&S.agg[m][Dd + kk * Dd + dg * 4]) = ag;
            if (kk == 0) {
                *reinterpret_cast<float4*>(&S.agg[m][dg * 4]) = make_float4(f0, f1, f2, f3);
            }
        }
    }
    __syncthreads();

    // ---------------- MLP: y[m][o] = relu(bias + agg . W) ----------------
    const int og  = tid & 15;   // o-group: 4 outputs
    const int mg2 = tid >> 4;   // m-group: 8 rows
    float4 y[8];
    #pragma unroll
    for (int i = 0; i < 8; ++i) y[i] = make_float4(0.f, 0.f, 0.f, 0.f);

    #pragma unroll 4
    for (int c = 0; c < CC; c += 4) {
        const float4 w0 = *reinterpret_cast<const float4*>(&S.Wt[c + 0][og * 4]);
        const float4 w1 = *reinterpret_cast<const float4*>(&S.Wt[c + 1][og * 4]);
        const float4 w2 = *reinterpret_cast<const float4*>(&S.Wt[c + 2][og * 4]);
        const float4 w3 = *reinterpret_cast<const float4*>(&S.Wt[c + 3][og * 4]);
        #pragma unroll
        for (int i = 0; i < 8; ++i) {
            const float4 a = *reinterpret_cast<const float4*>(&S.agg[mg2 * 8 + i][c]);
            y[i].x = fmaf(a.x, w0.x, fmaf(a.y, w1.x, fmaf(a.z, w2.x, fmaf(a.w, w3.x, y[i].x))));
            y[i].y = fmaf(a.x, w0.y, fmaf(a.y, w1.y, fmaf(a.z, w2.y, fmaf(a.w, w3.y, y[i].y))));
            y[i].z = fmaf(a.x, w0.z, fmaf(a.y, w1.z, fmaf(a.z, w2.z, fmaf(a.w, w3.z, y[i].z))));
            y[i].w = fmaf(a.x, w0.w, fmaf(a.y, w1.w, fmaf(a.z, w2.w, fmaf(a.w, w3.w, y[i].w))));
        }
    }

    const float bx = bm[og * 4 + 0];
    const float by = bm[og * 4 + 1];
    const float bz = bm[og * 4 + 2];
    const float bw = bm[og * 4 + 3];
    float* ob = out + (size_t)((b * Mm + mt * BM) * CO) * Tt + t;
    #pragma unroll
    for (int i = 0; i < 8; ++i) {
        const int m = mg2 * 8 + i;
        float* op = ob + (size_t)(m * CO + og * 4) * Tt;
        op[0]      = fmaxf(y[i].x + bx, 0.f);
        op[Tt]     = fmaxf(y[i].y + by, 0.f);
        op[2 * Tt] = fmaxf(y[i].z + bz, 0.f);
        op[3 * Tt] = fmaxf(y[i].w + bw, 0.f);
    }
}

} // namespace

extern "C" void kernel_launch(void* const* d_in, const int* in_sizes, int n_in,
                              void* d_out, int out_size) {
    const float* fc   = (const float*)d_in[0];  // feat_context [2,512,32,128]
    const float* ft   = (const float*)d_in[1];  // feat_target  [2,256,32,128]
    const float* adj  = (const float*)d_in[2];  // adj          [2,2,256,512]
    const float* mask = (const float*)d_in[3];  // mask         [2,128,512]
    const float* Wm   = (const float*)d_in[4];  // W_mlp        [64,96]
    const float* bm   = (const float*)d_in[5];  // b_mlp        [64]
    float* out = (float*)d_out;                 // [2,256,64,128]

    cudaFuncSetAttribute(graph_agg_kernel,
                         cudaFuncAttributeMaxDynamicSharedMemorySize, SMEM_BYTES);
    dim3 grid(Tt, Mm / BM, Bb);
    graph_agg_kernel<<<grid, BDIM, SMEM_BYTES>>>(fc, ft, adj, mask, Wm, bm, out);
}